// round 2
// baseline (speedup 1.0000x reference)
#include <cuda_runtime.h>

// MultiScaleDeformableAttention
// value:               (8, 22223, 8, 32) f32
// sampling_locations:  (8, 900, 8, 4, 4, 2) f32
// attention_weights:   (8, 900, 8, 4, 4) f32
// out:                 (8, 900, 256) f32  == (b, q, h, d)

#define BS   8
#define NQ   900
#define NH   8
#define D    32
#define NL   4
#define NPT  4
#define NUM_KEYS 22223

__global__ void __launch_bounds__(256) msda_kernel(
    const float* __restrict__ value,
    const float* __restrict__ loc,
    const float* __restrict__ aw,
    float* __restrict__ out)
{
    const int tid = blockIdx.x * blockDim.x + threadIdx.x;
    const int total = BS * NQ * NH * (D / 4);
    if (tid >= total) return;

    const int chunk = tid & 7;        // which float4 of the 32-channel vector
    const int bqh   = tid >> 3;
    const int h     = bqh % NH;
    const int bq    = bqh / NH;
    const int q     = bq % NQ;
    const int b     = bq / NQ;

    // sampling locations / weights for this (b,q,h)
    const float4* loc_p = (const float4*)(loc + (((b * NQ + q) * NH + h) * NL * NPT) * 2);
    const float4* aw_p  = (const float4*)(aw  + (((b * NQ + q) * NH + h) * NL * NPT));

    // value base for this (b, h), offset to this thread's channel chunk
    const float* vbase = value + (b * NUM_KEYS * NH + h) * D + chunk * 4;

    const int   Hs[NL]  = {100, 50, 25, 13};
    const int   Ws[NL]  = {167, 84, 42, 21};
    const int   St[NL]  = {0, 16700, 20900, 21950};

    float4 acc = make_float4(0.f, 0.f, 0.f, 0.f);

    #pragma unroll
    for (int l = 0; l < NL; ++l) {
        const int H = Hs[l];
        const int W = Ws[l];
        const float* vlvl = vbase + St[l] * (NH * D);

        // 8 loc floats (4 points x,y) + 4 weights for this level, vectorized
        const float4 lc0 = loc_p[l * 2 + 0];   // p0.x p0.y p1.x p1.y
        const float4 lc1 = loc_p[l * 2 + 1];   // p2.x p2.y p3.x p3.y
        const float4 wv  = aw_p[l];

        const float px[NPT] = {lc0.x, lc0.z, lc1.x, lc1.z};
        const float py[NPT] = {lc0.y, lc0.w, lc1.y, lc1.w};
        const float pw[NPT] = {wv.x, wv.y, wv.z, wv.w};

        #pragma unroll
        for (int p = 0; p < NPT; ++p) {
            const float x = px[p] * (float)W - 0.5f;
            const float y = py[p] * (float)H - 0.5f;
            const float xf = floorf(x);
            const float yf = floorf(y);
            const int x0 = (int)xf;
            const int y0 = (int)yf;
            const float tx = x - xf;
            const float ty = y - yf;

            // validity folded into weights (branch-free); loads use clamped idx
            const float wx0 = (x0 >= 0 && x0 < W)         ? (1.f - tx) : 0.f;
            const float wx1 = (x0 + 1 >= 0 && x0 + 1 < W) ? tx         : 0.f;
            const float wy0 = (y0 >= 0 && y0 < H)         ? (1.f - ty) : 0.f;
            const float wy1 = (y0 + 1 >= 0 && y0 + 1 < H) ? ty         : 0.f;

            const int xc0 = min(max(x0,     0), W - 1);
            const int xc1 = min(max(x0 + 1, 0), W - 1);
            const int yc0 = min(max(y0,     0), H - 1);
            const int yc1 = min(max(y0 + 1, 0), H - 1);

            const int r0 = yc0 * W;
            const int r1 = yc1 * W;

            // 4 independent unconditional 128-bit loads -> high MLP
            const float4 v00 = *(const float4*)(vlvl + (r0 + xc0) * (NH * D));
            const float4 v10 = *(const float4*)(vlvl + (r0 + xc1) * (NH * D));
            const float4 v01 = *(const float4*)(vlvl + (r1 + xc0) * (NH * D));
            const float4 v11 = *(const float4*)(vlvl + (r1 + xc1) * (NH * D));

            const float wa  = pw[p];
            const float w00 = wx0 * wy0 * wa;
            const float w10 = wx1 * wy0 * wa;
            const float w01 = wx0 * wy1 * wa;
            const float w11 = wx1 * wy1 * wa;

            acc.x += w00 * v00.x + w10 * v10.x + w01 * v01.x + w11 * v11.x;
            acc.y += w00 * v00.y + w10 * v10.y + w01 * v01.y + w11 * v11.y;
            acc.z += w00 * v00.z + w10 * v10.z + w01 * v01.z + w11 * v11.z;
            acc.w += w00 * v00.w + w10 * v10.w + w01 * v01.w + w11 * v11.w;
        }
    }

    float* op = out + ((b * NQ + q) * NH + h) * D + chunk * 4;
    *(float4*)op = acc;
}

extern "C" void kernel_launch(void* const* d_in, const int* in_sizes, int n_in,
                              void* d_out, int out_size)
{
    const float* value = (const float*)d_in[0];
    const float* loc   = (const float*)d_in[1];
    const float* aw    = (const float*)d_in[2];
    float* out = (float*)d_out;

    const int total = BS * NQ * NH * (D / 4);   // 460800
    const int block = 256;
    const int grid  = (total + block - 1) / block;
    msda_kernel<<<grid, block>>>(value, loc, aw, out);
}